// round 15
// baseline (speedup 1.0000x reference)
#include <cuda_runtime.h>
#include <cuda_fp16.h>
#include <cuda_fp8.h>
#include <math.h>
#include <stdint.h>

// ---------------------------------------------------------------------------
#define D        256
#define N_NODES  4000
#define LL       3
#define VV       2

#define Q_ROWS     8640
#define TOTAL_ROWS 10800
#define N_ANCHORS  1440

#define PROJ_BLOCKS 85      // ceil(10800 / 128)
#define ROWS_PB     128
#define FPITCH      272     // fp8 tile pitch in bytes (256B data + 16 pad)

#define LOSS_BLOCKS 168

__device__ unsigned short g_proj8[(size_t)TOTAL_ROWS * 128];  // e4m3x2 proj rows
__device__ float g_pos[N_ANCHORS];
__device__ float g_neg[N_ANCHORS];
__device__ unsigned int g_ctr;

// ---------------------------------------------------------------------------
__device__ __forceinline__ uint32_t smem_u32(const void* p) {
    uint32_t a;
    asm("{ .reg .u64 t; cvta.to.shared.u64 t, %1; cvt.u32.u64 %0, t; }"
        : "=r"(a) : "l"(p));
    return a;
}
__device__ __forceinline__ void ldsm_x4(uint32_t* r, uint32_t addr) {
    asm volatile("ldmatrix.sync.aligned.m8n8.x4.shared.b16 {%0,%1,%2,%3}, [%4];"
                 : "=r"(r[0]), "=r"(r[1]), "=r"(r[2]), "=r"(r[3]) : "r"(addr));
}
__device__ __forceinline__ void mma16832fp8(float* c, const uint32_t* a,
                                            const uint32_t* b) {
    asm volatile("mma.sync.aligned.m16n8k32.row.col.f32.e4m3.e4m3.f32 "
                 "{%0,%1,%2,%3}, {%4,%5,%6,%7}, {%8,%9}, {%0,%1,%2,%3};"
                 : "+f"(c[0]), "+f"(c[1]), "+f"(c[2]), "+f"(c[3])
                 : "r"(a[0]), "r"(a[1]), "r"(a[2]), "r"(a[3]),
                   "r"(b[0]), "r"(b[1]));
}
__device__ __forceinline__ unsigned short pack_e4m3x2(float x, float y) {
    __nv_fp8x2_e4m3 f8(make_float2(x, y));
    return *reinterpret_cast<unsigned short*>(&f8);
}
__device__ __forceinline__ unsigned int pack_e4m3x4(float4 v) {
    __nv_fp8x4_e4m3 f8(v);
    return *reinterpret_cast<unsigned int*>(&f8);
}

// ---------------------------------------------------------------------------
__device__ __forceinline__ const float* map_src_row(
    int r, const float* __restrict__ E,
    const int* __restrict__ idxp, const int* __restrict__ idxr,
    const int* __restrict__ negp, const int* __restrict__ negr)
{
    if (r < Q_ROWS) {
        int t, local, S;
        if (r < 3600)      { t = 0; local = r;        S = 100; }
        else if (r < 7200) { t = 1; local = r - 3600; S = 100; }
        else if (r < 7920) { t = 2; local = r - 7200; S = 20;  }
        else               { t = 3; local = r - 7920; S = 20;  }
        int perxy = 6 * S;
        int xy  = local / perxy;
        int rem = local - xy * perxy;
        int node = (t < 2) ? idxp[t * 600 + rem] : idxr[(t - 2) * 120 + rem];
        int x = xy / LL, y = xy - x * LL;
        return E + ((size_t)(((t * VV + x) * LL + y) * N_NODES + node)) * D;
    } else {
        int rr = r - Q_ROWS;
        int t, local, K;
        if (rr < 900)       { t = 0; local = rr;        K = 50; }
        else if (rr < 1800) { t = 1; local = rr - 900;  K = 50; }
        else if (rr < 1980) { t = 2; local = rr - 1800; K = 10; }
        else                { t = 3; local = rr - 1980; K = 10; }
        int perO = 6 * K;
        int o   = local / perO;
        int vlk = local - o * perO;
        int vl  = vlk / K;
        int k   = vlk - vl * K;
        int off = (vl * 3 + o) * K + k;
        int node = (t < 2) ? negp[t * 900 + off] : negr[(t - 2) * 180 + off];
        int ot = o + (o >= t ? 1 : 0);
        int v = vl / LL, l = vl - v * LL;
        return E + ((size_t)(((ot * VV + v) * LL + l) * N_NODES + node)) * D;
    }
}

// ---------------------------------------------------------------------------
// Projection, full e4m3: 85 blocks x 512 thr (16 warps: 4 my x 4 cx).
// X, W, H all e4m3; m16n8k32 MMA; fp32 accum; epilogue normalizes + e4m3 out.
#define SMA   0
#define SMW   34816                 // A: 128*272
#define CTRL  104448                // + W: 256*272
#define SM_BYTES (CTRL + 1024 + 1024 + 1024 + 2048)

__global__ void __launch_bounds__(512, 1)
proj_mma_kernel(const float* __restrict__ E,
                const float* __restrict__ W1, const float* __restrict__ b1,
                const float* __restrict__ W2, const float* __restrict__ b2,
                const int* __restrict__ idxp, const int* __restrict__ idxr,
                const int* __restrict__ negp, const int* __restrict__ negr)
{
    extern __shared__ char sm[];
    const uint32_t smb = smem_u32(sm);

    float* smb1 = (float*)(sm + CTRL);
    float* smb2 = (float*)(sm + CTRL + 1024);
    const float** srcp = (const float**)(sm + CTRL + 2048);
    float* ssbuf = (float*)(sm + CTRL + 3072);   // [128][4]

    const int tid = threadIdx.x;
    const int l   = tid & 31;
    const int w   = tid >> 5;
    const int my  = w >> 2;          // 0..3
    const int cx  = w & 3;           // 0..3
    const int r0  = blockIdx.x * ROWS_PB;

    if (blockIdx.x == 0) {
        for (int i = tid; i < N_ANCHORS; i += 512) { g_pos[i] = 0.f; g_neg[i] = 0.f; }
        if (tid == 0) g_ctr = 0u;
    }

    if (tid < 64)        ((float4*)smb1)[tid]      = ((const float4*)b1)[tid];
    else if (tid < 128)  ((float4*)smb2)[tid - 64] = ((const float4*)b2)[tid - 64];
    if (tid < ROWS_PB) {
        int r = r0 + tid;
        srcp[tid] = (r < TOTAL_ROWS)
                  ? map_src_row(r, E, idxp, idxr, negp, negr)
                  : (const float*)0;
    }

    // W1 fp32 -> e4m3 smem tile (256 rows x 16 x 16B segments)
    for (int i = tid; i < 4096; i += 512) {
        int n = i >> 4, q = i & 15;
        const float4* src = (const float4*)(W1 + n * 256 + q * 16);
        uint4 pk;
        pk.x = pack_e4m3x4(src[0]);
        pk.y = pack_e4m3x4(src[1]);
        pk.z = pack_e4m3x4(src[2]);
        pk.w = pack_e4m3x4(src[3]);
        *(uint4*)(sm + SMW + n * FPITCH + q * 16) = pk;
    }
    __syncthreads();

    // gather X -> e4m3 A tile (16 segments of 16B per row)
    for (int i = tid; i < ROWS_PB * 16; i += 512) {
        int m = i >> 4, q = i & 15;
        const float* s = srcp[m];
        uint4 pk = make_uint4(0u, 0u, 0u, 0u);
        if (s) {
            const float4* s4 = (const float4*)(s + q * 16);
            pk.x = pack_e4m3x4(s4[0]);
            pk.y = pack_e4m3x4(s4[1]);
            pk.z = pack_e4m3x4(s4[2]);
            pk.w = pack_e4m3x4(s4[3]);
        }
        *(uint4*)(sm + SMA + m * FPITCH + q * 16) = pk;
    }
    __syncthreads();

    const uint32_t a_base = smb + SMA +
        (my * 32 + ((l >> 3) & 1) * 8 + (l & 7)) * FPITCH + (l >> 4) * 16;
    const uint32_t b_base = smb + SMW +
        (cx * 64 + ((l >> 4) & 1) * 8 + (l & 7)) * FPITCH + ((l >> 3) & 1) * 16;

    const int g  = l >> 2;
    const int q2 = (l & 3) * 2;

    float c[2][8][4];

    // =================== layer 1 ===================
    #pragma unroll
    for (int mt = 0; mt < 2; mt++)
        #pragma unroll
        for (int nt = 0; nt < 8; nt++)
            #pragma unroll
            for (int j = 0; j < 4; j++) c[mt][nt][j] = 0.f;

    #pragma unroll
    for (int kk = 0; kk < 8; kk++) {
        uint32_t a[8];
        ldsm_x4(a,     a_base + kk * 32);
        ldsm_x4(a + 4, a_base + kk * 32 + 16 * FPITCH);
        #pragma unroll
        for (int ntp = 0; ntp < 4; ntp++) {
            uint32_t b4[4];
            ldsm_x4(b4, b_base + kk * 32 + ntp * 16 * FPITCH);
            mma16832fp8(c[0][2*ntp],   a,     b4);
            mma16832fp8(c[1][2*ntp],   a + 4, b4);
            mma16832fp8(c[0][2*ntp+1], a,     b4 + 2);
            mma16832fp8(c[1][2*ntp+1], a + 4, b4 + 2);
        }
    }
    __syncthreads();

    // epilogue 1: bias + relu -> e4m3 H into A tile
    #pragma unroll
    for (int mt = 0; mt < 2; mt++) {
        #pragma unroll
        for (int nt = 0; nt < 8; nt++) {
            int col = cx * 64 + nt * 8 + q2;
            float bx = smb1[col], by = smb1[col + 1];
            int rlo = my * 32 + mt * 16 + g;
            *(unsigned short*)(sm + SMA + rlo * FPITCH + col) =
                pack_e4m3x2(fmaxf(c[mt][nt][0] + bx, 0.f),
                            fmaxf(c[mt][nt][1] + by, 0.f));
            *(unsigned short*)(sm + SMA + (rlo + 8) * FPITCH + col) =
                pack_e4m3x2(fmaxf(c[mt][nt][2] + bx, 0.f),
                            fmaxf(c[mt][nt][3] + by, 0.f));
        }
    }
    // W2 fp32 -> e4m3 smem tile
    for (int i = tid; i < 4096; i += 512) {
        int n = i >> 4, q = i & 15;
        const float4* src = (const float4*)(W2 + n * 256 + q * 16);
        uint4 pk;
        pk.x = pack_e4m3x4(src[0]);
        pk.y = pack_e4m3x4(src[1]);
        pk.z = pack_e4m3x4(src[2]);
        pk.w = pack_e4m3x4(src[3]);
        *(uint4*)(sm + SMW + n * FPITCH + q * 16) = pk;
    }
    __syncthreads();

    // =================== layer 2 ===================
    #pragma unroll
    for (int mt = 0; mt < 2; mt++)
        #pragma unroll
        for (int nt = 0; nt < 8; nt++)
            #pragma unroll
            for (int j = 0; j < 4; j++) c[mt][nt][j] = 0.f;

    #pragma unroll
    for (int kk = 0; kk < 8; kk++) {
        uint32_t a[8];
        ldsm_x4(a,     a_base + kk * 32);
        ldsm_x4(a + 4, a_base + kk * 32 + 16 * FPITCH);
        #pragma unroll
        for (int ntp = 0; ntp < 4; ntp++) {
            uint32_t b4[4];
            ldsm_x4(b4, b_base + kk * 32 + ntp * 16 * FPITCH);
            mma16832fp8(c[0][2*ntp],   a,     b4);
            mma16832fp8(c[1][2*ntp],   a + 4, b4);
            mma16832fp8(c[0][2*ntp+1], a,     b4 + 2);
            mma16832fp8(c[1][2*ntp+1], a + 4, b4 + 2);
        }
    }

    // epilogue 2: bias, row L2-norm, e4m3 store
    float ss[4] = {0.f, 0.f, 0.f, 0.f};
    #pragma unroll
    for (int mt = 0; mt < 2; mt++) {
        #pragma unroll
        for (int nt = 0; nt < 8; nt++) {
            int col = cx * 64 + nt * 8 + q2;
            float bx = smb2[col], by = smb2[col + 1];
            float z0 = c[mt][nt][0] + bx, z1 = c[mt][nt][1] + by;
            float z2 = c[mt][nt][2] + bx, z3 = c[mt][nt][3] + by;
            ss[mt * 2]     += z0 * z0 + z1 * z1;
            ss[mt * 2 + 1] += z2 * z2 + z3 * z3;
        }
    }
    #pragma unroll
    for (int j = 0; j < 4; j++) {
        ss[j] += __shfl_xor_sync(0xffffffffu, ss[j], 1);
        ss[j] += __shfl_xor_sync(0xffffffffu, ss[j], 2);
    }
    if ((l & 3) == 0) {
        #pragma unroll
        for (int j = 0; j < 4; j++) {
            int row = my * 32 + (j >> 1) * 16 + (j & 1) * 8 + g;
            ssbuf[row * 4 + cx] = ss[j];
        }
    }
    __syncthreads();

    float inv[4];
    #pragma unroll
    for (int j = 0; j < 4; j++) {
        int row = my * 32 + (j >> 1) * 16 + (j & 1) * 8 + g;
        float t = ssbuf[row * 4 + 0] + ssbuf[row * 4 + 1]
                + ssbuf[row * 4 + 2] + ssbuf[row * 4 + 3];
        inv[j] = 1.0f / fmaxf(sqrtf(t), 1e-12f);
    }

    #pragma unroll
    for (int mt = 0; mt < 2; mt++) {
        #pragma unroll
        for (int nt = 0; nt < 8; nt++) {
            int col = cx * 64 + nt * 8 + q2;
            float bx = smb2[col], by = smb2[col + 1];
            int rlo = r0 + my * 32 + mt * 16 + g;
            int rhi = rlo + 8;
            int ci = (col >> 1);
            if (rlo < TOTAL_ROWS)
                g_proj8[(size_t)rlo * 128 + ci] =
                    pack_e4m3x2((c[mt][nt][0] + bx) * inv[mt * 2],
                                (c[mt][nt][1] + by) * inv[mt * 2]);
            if (rhi < TOTAL_ROWS)
                g_proj8[(size_t)rhi * 128 + ci] =
                    pack_e4m3x2((c[mt][nt][2] + bx) * inv[mt * 2 + 1],
                                (c[mt][nt][3] + by) * inv[mt * 2 + 1]);
        }
    }
}

// ---------------------------------------------------------------------------
// Loss (R14): 168 blocks x 512 threads, M64 x N128 x K256 in e4m3 (m16n8k32).
#define LSMA 0
#define LSMB 17408                 // A: 64*272
#define LTRG 52224                 // B: 128*272
#define LSM_BYTES (LTRG + 512 + 512 + 128)

__global__ void __launch_bounds__(512)
loss_mma_kernel(float* __restrict__ out)
{
    extern __shared__ char sm[];
    const uint32_t smb = smem_u32(sm);
    int* targ  = (int*)(sm + LTRG);
    int* tinfo = (int*)(sm + LTRG + 512);

    const int tid = threadIdx.x;
    const int l   = tid & 31;
    const int w   = tid >> 5;
    const int my  = w >> 3;          // 0..1
    const int cx  = w & 7;           // 0..7
    const int b   = blockIdx.x;

    int S, K, vl, chunk, mtile, qbase, pbase, aid0;
    if (b < 144) {
        int t = b / 72, rem = b % 72;
        vl = rem / 12;
        int r2 = rem % 12;
        mtile = r2 / 6; chunk = r2 % 6;
        S = 100; K = 50;
        qbase = t * 3600; pbase = t * 900;
        aid0  = t * 600 + vl * 100;
    } else {
        int bs = b - 144;
        int t2 = bs / 12;
        int rem = bs % 12;
        vl = rem / 2; chunk = rem % 2; mtile = 0;
        S = 20; K = 10;
        qbase = 7200 + t2 * 720; pbase = 1800 + t2 * 180;
        aid0  = 1200 + t2 * 120 + vl * 20;
    }
    const int NTARG = 6 * S + 3 * K;
    const int diag_base = qbase + vl * 7 * S;
    const int mrow0 = mtile * 64;

    if (tid < 128) {
        int n = chunk * 128 + tid;
        int row = 0, info = 0;
        if (n < 6 * S) {
            int xy = n / S, ts = n - xy * S;
            row  = qbase + (xy * 6 + vl) * S + ts;
            info = ts | ((xy == vl) ? 0x10000 : 0) | 0x40000;
        } else if (n < NTARG) {
            int cc = n - 6 * S;
            int o = cc / K, k = cc - o * K;
            row  = Q_ROWS + pbase + (o * 6 + vl) * K + k;
            info = 0x20000 | 0x40000;
        }
        targ[tid]  = row;
        tinfo[tid] = info;
    }
    __syncthreads();

    for (int i = tid; i < 64 * 16; i += 512) {
        int r = i >> 4, q = i & 15;
        int gr = mrow0 + r;
        int arow = diag_base + (gr < S ? gr : 0);
        *(float4*)(sm + LSMA + r * FPITCH + q * 16) =
            ((const float4*)g_proj8)[(size_t)arow * 16 + q];
    }
    for (int i = tid; i < 128 * 16; i += 512) {
        int r = i >> 4, q = i & 15;
        *(float4*)(sm + LSMB + r * FPITCH + q * 16) =
            ((const float4*)g_proj8)[(size_t)targ[r] * 16 + q];
    }
    __syncthreads();

    const uint32_t a_base = smb + LSMA +
        (my * 32 + ((l >> 3) & 1) * 8 + (l & 7)) * FPITCH + (l >> 4) * 16;
    const uint32_t b_base = smb + LSMB +
        (cx * 16 + ((l >> 4) & 1) * 8 + (l & 7)) * FPITCH + ((l >> 3) & 1) * 16;

    float c[2][2][4];
    #pragma unroll
    for (int mt = 0; mt < 2; mt++)
        #pragma unroll
        for (int nt = 0; nt < 2; nt++)
            #pragma unroll
            for (int j = 0; j < 4; j++) c[mt][nt][j] = 0.f;

    #pragma unroll
    for (int kk = 0; kk < 8; kk++) {
        uint32_t a[8];
        ldsm_x4(a,     a_base + kk * 32);
        ldsm_x4(a + 4, a_base + kk * 32 + 16 * FPITCH);
        uint32_t b4[4];
        ldsm_x4(b4, b_base + kk * 32);
        mma16832fp8(c[0][0], a,     b4);
        mma16832fp8(c[1][0], a + 4, b4);
        mma16832fp8(c[0][1], a,     b4 + 2);
        mma16832fp8(c[1][1], a + 4, b4 + 2);
    }

    const int g  = l >> 2;
    const int q2 = (l & 3) * 2;
    float pacc[4] = {0.f, 0.f, 0.f, 0.f};
    float nacc[4] = {0.f, 0.f, 0.f, 0.f};

    int rowg[4];
    #pragma unroll
    for (int s = 0; s < 4; s++)
        rowg[s] = mrow0 + my * 32 + (s >> 1) * 16 + (s & 1) * 8 + g;

    #pragma unroll
    for (int nt = 0; nt < 2; nt++) {
        #pragma unroll
        for (int jl = 0; jl < 2; jl++) {
            int info = tinfo[cx * 16 + nt * 8 + q2 + jl];
            if (info & 0x40000) {
                int ts = info & 0xFFFF;
                #pragma unroll
                for (int mt = 0; mt < 2; mt++) {
                    #pragma unroll
                    for (int jh = 0; jh < 2; jh++) {
                        int s = mt * 2 + jh;
                        if (rowg[s] < S) {
                            float e = __expf(2.0f * c[mt][nt][jh * 2 + jl]);
                            if (info & 0x20000)        nacc[s] += e;
                            else if (info & 0x10000) { if (ts != rowg[s]) nacc[s] += e; }
                            else if (ts == rowg[s])    pacc[s] += e;
                        }
                    }
                }
            }
        }
    }

    #pragma unroll
    for (int s = 0; s < 4; s++) {
        pacc[s] += __shfl_xor_sync(0xffffffffu, pacc[s], 1);
        pacc[s] += __shfl_xor_sync(0xffffffffu, pacc[s], 2);
        nacc[s] += __shfl_xor_sync(0xffffffffu, nacc[s], 1);
        nacc[s] += __shfl_xor_sync(0xffffffffu, nacc[s], 2);
    }
    if ((l & 3) == 0) {
        #pragma unroll
        for (int s = 0; s < 4; s++) {
            if (rowg[s] < S) {
                if (pacc[s] != 0.f) atomicAdd(&g_pos[aid0 + rowg[s]], pacc[s]);
                if (nacc[s] != 0.f) atomicAdd(&g_neg[aid0 + rowg[s]], nacc[s]);
            }
        }
    }

    // ---- fused finalize ----
    __shared__ unsigned int is_last;
    __threadfence();
    __syncthreads();
    if (tid == 0)
        is_last = (atomicAdd(&g_ctr, 1u) == (unsigned)(gridDim.x - 1));
    __syncthreads();
    if (is_last) {
        float loc = 0.f;
        for (int i = tid; i < N_ANCHORS; i += 512) {
            float p = g_pos[i], n = g_neg[i];
            loc += -logf(p / (p + n));
        }
        loc += __shfl_xor_sync(0xffffffffu, loc, 16);
        loc += __shfl_xor_sync(0xffffffffu, loc, 8);
        loc += __shfl_xor_sync(0xffffffffu, loc, 4);
        loc += __shfl_xor_sync(0xffffffffu, loc, 2);
        loc += __shfl_xor_sync(0xffffffffu, loc, 1);
        float* red = (float*)(sm + LTRG + 1024);
        if (l == 0) red[w] = loc;
        __syncthreads();
        if (w == 0) {
            float s = (l < 16) ? red[l] : 0.f;
            s += __shfl_xor_sync(0xffffffffu, s, 8);
            s += __shfl_xor_sync(0xffffffffu, s, 4);
            s += __shfl_xor_sync(0xffffffffu, s, 2);
            s += __shfl_xor_sync(0xffffffffu, s, 1);
            if (l == 0) out[0] = s * (1.0f / 1440.0f);
        }
    }
}

// ---------------------------------------------------------------------------
extern "C" void kernel_launch(void* const* d_in, const int* in_sizes, int n_in,
                              void* d_out, int out_size)
{
    const float* E    = (const float*)d_in[0];
    const float* W1   = (const float*)d_in[1];
    const float* b1   = (const float*)d_in[2];
    const float* W2   = (const float*)d_in[3];
    const float* b2   = (const float*)d_in[4];
    const int*   idxp = (const int*)d_in[5];
    const int*   idxr = (const int*)d_in[6];
    const int*   negp = (const int*)d_in[7];
    const int*   negr = (const int*)d_in[8];
    float* out = (float*)d_out;
    (void)in_sizes; (void)n_in; (void)out_size;

    cudaFuncSetAttribute(proj_mma_kernel,
                         cudaFuncAttributeMaxDynamicSharedMemorySize, SM_BYTES);
    cudaFuncSetAttribute(loss_mma_kernel,
                         cudaFuncAttributeMaxDynamicSharedMemorySize, LSM_BYTES);

    proj_mma_kernel<<<PROJ_BLOCKS, 512, SM_BYTES>>>(E, W1, b1, W2, b2,
                                                    idxp, idxr, negp, negr);
    loss_mma_kernel<<<LOSS_BLOCKS, 512, LSM_BYTES>>>(out);
}

// round 16
// speedup vs baseline: 1.1316x; 1.1316x over previous
#include <cuda_runtime.h>
#include <cuda_fp16.h>
#include <cuda_fp8.h>
#include <math.h>
#include <stdint.h>

// ---------------------------------------------------------------------------
#define D        256
#define N_NODES  4000
#define LL       3
#define VV       2

#define Q_ROWS     8640
#define TOTAL_ROWS 10800
#define N_ANCHORS  1440

#define PROJ_BLOCKS 85      // ceil(10800 / 128)
#define ROWS_PB     128
#define APITCH      264     // fp16 tile pitch in halfs (528 B rows)
#define FPITCH      272     // fp8 tile pitch in bytes (256B data + 16 pad)

#define LOSS_BLOCKS 168

__device__ unsigned short g_proj8[(size_t)TOTAL_ROWS * 128];  // e4m3x2 proj rows
__device__ float g_pos[N_ANCHORS];
__device__ float g_neg[N_ANCHORS];
__device__ unsigned int g_ctr;

// ---------------------------------------------------------------------------
__device__ __forceinline__ uint32_t smem_u32(const void* p) {
    uint32_t a;
    asm("{ .reg .u64 t; cvta.to.shared.u64 t, %1; cvt.u32.u64 %0, t; }"
        : "=r"(a) : "l"(p));
    return a;
}
__device__ __forceinline__ void ldsm_x4(uint32_t* r, uint32_t addr) {
    asm volatile("ldmatrix.sync.aligned.m8n8.x4.shared.b16 {%0,%1,%2,%3}, [%4];"
                 : "=r"(r[0]), "=r"(r[1]), "=r"(r[2]), "=r"(r[3]) : "r"(addr));
}
__device__ __forceinline__ void mma16816(float* c, const uint32_t* a,
                                         const uint32_t* b) {
    asm volatile("mma.sync.aligned.m16n8k16.row.col.f32.f16.f16.f32 "
                 "{%0,%1,%2,%3}, {%4,%5,%6,%7}, {%8,%9}, {%0,%1,%2,%3};"
                 : "+f"(c[0]), "+f"(c[1]), "+f"(c[2]), "+f"(c[3])
                 : "r"(a[0]), "r"(a[1]), "r"(a[2]), "r"(a[3]),
                   "r"(b[0]), "r"(b[1]));
}
__device__ __forceinline__ void mma16832fp8(float* c, const uint32_t* a,
                                            const uint32_t* b) {
    asm volatile("mma.sync.aligned.m16n8k32.row.col.f32.e4m3.e4m3.f32 "
                 "{%0,%1,%2,%3}, {%4,%5,%6,%7}, {%8,%9}, {%0,%1,%2,%3};"
                 : "+f"(c[0]), "+f"(c[1]), "+f"(c[2]), "+f"(c[3])
                 : "r"(a[0]), "r"(a[1]), "r"(a[2]), "r"(a[3]),
                   "r"(b[0]), "r"(b[1]));
}
__device__ __forceinline__ unsigned short pack_e4m3x2(float x, float y) {
    __nv_fp8x2_e4m3 f8(make_float2(x, y));
    return *reinterpret_cast<unsigned short*>(&f8);
}

// ---------------------------------------------------------------------------
__device__ __forceinline__ const float* map_src_row(
    int r, const float* __restrict__ E,
    const int* __restrict__ idxp, const int* __restrict__ idxr,
    const int* __restrict__ negp, const int* __restrict__ negr)
{
    if (r < Q_ROWS) {
        int t, local, S;
        if (r < 3600)      { t = 0; local = r;        S = 100; }
        else if (r < 7200) { t = 1; local = r - 3600; S = 100; }
        else if (r < 7920) { t = 2; local = r - 7200; S = 20;  }
        else               { t = 3; local = r - 7920; S = 20;  }
        int perxy = 6 * S;
        int xy  = local / perxy;
        int rem = local - xy * perxy;
        int node = (t < 2) ? idxp[t * 600 + rem] : idxr[(t - 2) * 120 + rem];
        int x = xy / LL, y = xy - x * LL;
        return E + ((size_t)(((t * VV + x) * LL + y) * N_NODES + node)) * D;
    } else {
        int rr = r - Q_ROWS;
        int t, local, K;
        if (rr < 900)       { t = 0; local = rr;        K = 50; }
        else if (rr < 1800) { t = 1; local = rr - 900;  K = 50; }
        else if (rr < 1980) { t = 2; local = rr - 1800; K = 10; }
        else                { t = 3; local = rr - 1980; K = 10; }
        int perO = 6 * K;
        int o   = local / perO;
        int vlk = local - o * perO;
        int vl  = vlk / K;
        int k   = vlk - vl * K;
        int off = (vl * 3 + o) * K + k;
        int node = (t < 2) ? negp[t * 900 + off] : negr[(t - 2) * 180 + off];
        int ot = o + (o >= t ? 1 : 0);
        int v = vl / LL, l = vl - v * LL;
        return E + ((size_t)(((ot * VV + v) * LL + l) * N_NODES + node)) * D;
    }
}

// ---------------------------------------------------------------------------
// Projection (R14 measured-best): fp16 HMMA, x4 B loads, e4m3 output.
#define SMA   0
#define SMW   67584
#define CTRL  202752
#define SM_BYTES (CTRL + 3072 + 2048)

__global__ void __launch_bounds__(512, 1)
proj_mma_kernel(const float* __restrict__ E,
                const float* __restrict__ W1, const float* __restrict__ b1,
                const float* __restrict__ W2, const float* __restrict__ b2,
                const int* __restrict__ idxp, const int* __restrict__ idxr,
                const int* __restrict__ negp, const int* __restrict__ negr)
{
    extern __shared__ char sm[];
    const uint32_t smb = smem_u32(sm);

    float* smb1 = (float*)(sm + CTRL);
    float* smb2 = (float*)(sm + CTRL + 1024);
    const float** srcp = (const float**)(sm + CTRL + 2048);
    float* ssbuf = (float*)(sm + CTRL + 3072);   // [128][4]

    const int tid = threadIdx.x;
    const int l   = tid & 31;
    const int w   = tid >> 5;
    const int my  = w >> 2;          // 0..3
    const int cx  = w & 3;           // 0..3
    const int r0  = blockIdx.x * ROWS_PB;

    if (blockIdx.x == 0) {
        for (int i = tid; i < N_ANCHORS; i += 512) { g_pos[i] = 0.f; g_neg[i] = 0.f; }
        if (tid == 0) g_ctr = 0u;
    }

    if (tid < 64)        ((float4*)smb1)[tid]      = ((const float4*)b1)[tid];
    else if (tid < 128)  ((float4*)smb2)[tid - 64] = ((const float4*)b2)[tid - 64];
    if (tid < ROWS_PB) {
        int r = r0 + tid;
        srcp[tid] = (r < TOTAL_ROWS)
                  ? map_src_row(r, E, idxp, idxr, negp, negr)
                  : (const float*)0;
    }

    // W1 fp32 -> fp16 smem tile
    for (int i = tid; i < 16384; i += 512) {
        int n = i >> 6, q = i & 63;
        float4 v = ((const float4*)W1)[i];
        __half2 p0 = __floats2half2_rn(v.x, v.y);
        __half2 p1 = __floats2half2_rn(v.z, v.w);
        uint2 pk = make_uint2(*reinterpret_cast<unsigned int*>(&p0),
                              *reinterpret_cast<unsigned int*>(&p1));
        *(uint2*)(sm + SMW + (n * APITCH + q * 4) * 2) = pk;
    }
    __syncthreads();

    // gather X -> fp16 A tile
    for (int i = tid; i < ROWS_PB * 64; i += 512) {
        int m = i >> 6, q = i & 63;
        const float* s = srcp[m];
        float4 v = make_float4(0.f, 0.f, 0.f, 0.f);
        if (s) v = ((const float4*)s)[q];
        __half2 p0 = __floats2half2_rn(v.x, v.y);
        __half2 p1 = __floats2half2_rn(v.z, v.w);
        uint2 pk = make_uint2(*reinterpret_cast<unsigned int*>(&p0),
                              *reinterpret_cast<unsigned int*>(&p1));
        *(uint2*)(sm + SMA + (m * APITCH + q * 4) * 2) = pk;
    }
    __syncthreads();

    const uint32_t a_base = smb + SMA +
        ((my * 32 + ((l >> 3) & 1) * 8 + (l & 7)) * APITCH + (l >> 4) * 8) * 2;
    const uint32_t b_base = smb + SMW +
        ((cx * 64 + ((l >> 4) & 1) * 8 + (l & 7)) * APITCH + ((l >> 3) & 1) * 8) * 2;

    float c[2][8][4];

    // layer 1
    #pragma unroll
    for (int mt = 0; mt < 2; mt++)
        #pragma unroll
        for (int nt = 0; nt < 8; nt++)
            #pragma unroll
            for (int j = 0; j < 4; j++) c[mt][nt][j] = 0.f;

    #pragma unroll 4
    for (int kk = 0; kk < 16; kk++) {
        uint32_t a[8];
        ldsm_x4(a,     a_base + kk * 32);
        ldsm_x4(a + 4, a_base + kk * 32 + 16 * APITCH * 2);
        #pragma unroll
        for (int ntp = 0; ntp < 4; ntp++) {
            uint32_t b4[4];
            ldsm_x4(b4, b_base + kk * 32 + ntp * 16 * APITCH * 2);
            mma16816(c[0][2*ntp],   a,     b4);
            mma16816(c[1][2*ntp],   a + 4, b4);
            mma16816(c[0][2*ntp+1], a,     b4 + 2);
            mma16816(c[1][2*ntp+1], a + 4, b4 + 2);
        }
    }
    __syncthreads();

    const int g  = l >> 2;
    const int q2 = (l & 3) * 2;
    #pragma unroll
    for (int mt = 0; mt < 2; mt++) {
        #pragma unroll
        for (int nt = 0; nt < 8; nt++) {
            int col = cx * 64 + nt * 8 + q2;
            float bx = smb1[col], by = smb1[col + 1];
            int rlo = my * 32 + mt * 16 + g;
            __half2 lo = __floats2half2_rn(fmaxf(c[mt][nt][0] + bx, 0.f),
                                           fmaxf(c[mt][nt][1] + by, 0.f));
            __half2 hi = __floats2half2_rn(fmaxf(c[mt][nt][2] + bx, 0.f),
                                           fmaxf(c[mt][nt][3] + by, 0.f));
            *(unsigned int*)(sm + SMA + (rlo * APITCH + col) * 2) =
                *reinterpret_cast<unsigned int*>(&lo);
            *(unsigned int*)(sm + SMA + ((rlo + 8) * APITCH + col) * 2) =
                *reinterpret_cast<unsigned int*>(&hi);
        }
    }
    // W2 fp32 -> fp16 smem tile
    for (int i = tid; i < 16384; i += 512) {
        int n = i >> 6, q = i & 63;
        float4 v = ((const float4*)W2)[i];
        __half2 p0 = __floats2half2_rn(v.x, v.y);
        __half2 p1 = __floats2half2_rn(v.z, v.w);
        uint2 pk = make_uint2(*reinterpret_cast<unsigned int*>(&p0),
                              *reinterpret_cast<unsigned int*>(&p1));
        *(uint2*)(sm + SMW + (n * APITCH + q * 4) * 2) = pk;
    }
    __syncthreads();

    // layer 2
    #pragma unroll
    for (int mt = 0; mt < 2; mt++)
        #pragma unroll
        for (int nt = 0; nt < 8; nt++)
            #pragma unroll
            for (int j = 0; j < 4; j++) c[mt][nt][j] = 0.f;

    #pragma unroll 4
    for (int kk = 0; kk < 16; kk++) {
        uint32_t a[8];
        ldsm_x4(a,     a_base + kk * 32);
        ldsm_x4(a + 4, a_base + kk * 32 + 16 * APITCH * 2);
        #pragma unroll
        for (int ntp = 0; ntp < 4; ntp++) {
            uint32_t b4[4];
            ldsm_x4(b4, b_base + kk * 32 + ntp * 16 * APITCH * 2);
            mma16816(c[0][2*ntp],   a,     b4);
            mma16816(c[1][2*ntp],   a + 4, b4);
            mma16816(c[0][2*ntp+1], a,     b4 + 2);
            mma16816(c[1][2*ntp+1], a + 4, b4 + 2);
        }
    }

    // epilogue: bias, row L2-norm, e4m3 store
    float ss[4] = {0.f, 0.f, 0.f, 0.f};
    #pragma unroll
    for (int mt = 0; mt < 2; mt++) {
        #pragma unroll
        for (int nt = 0; nt < 8; nt++) {
            int col = cx * 64 + nt * 8 + q2;
            float bx = smb2[col], by = smb2[col + 1];
            float z0 = c[mt][nt][0] + bx, z1 = c[mt][nt][1] + by;
            float z2 = c[mt][nt][2] + bx, z3 = c[mt][nt][3] + by;
            ss[mt * 2]     += z0 * z0 + z1 * z1;
            ss[mt * 2 + 1] += z2 * z2 + z3 * z3;
        }
    }
    #pragma unroll
    for (int j = 0; j < 4; j++) {
        ss[j] += __shfl_xor_sync(0xffffffffu, ss[j], 1);
        ss[j] += __shfl_xor_sync(0xffffffffu, ss[j], 2);
    }
    if ((l & 3) == 0) {
        #pragma unroll
        for (int j = 0; j < 4; j++) {
            int row = my * 32 + (j >> 1) * 16 + (j & 1) * 8 + g;
            ssbuf[row * 4 + cx] = ss[j];
        }
    }
    __syncthreads();

    float inv[4];
    #pragma unroll
    for (int j = 0; j < 4; j++) {
        int row = my * 32 + (j >> 1) * 16 + (j & 1) * 8 + g;
        float t = ssbuf[row * 4 + 0] + ssbuf[row * 4 + 1]
                + ssbuf[row * 4 + 2] + ssbuf[row * 4 + 3];
        inv[j] = 1.0f / fmaxf(sqrtf(t), 1e-12f);
    }

    #pragma unroll
    for (int mt = 0; mt < 2; mt++) {
        #pragma unroll
        for (int nt = 0; nt < 8; nt++) {
            int col = cx * 64 + nt * 8 + q2;
            float bx = smb2[col], by = smb2[col + 1];
            int rlo = r0 + my * 32 + mt * 16 + g;
            int rhi = rlo + 8;
            int ci = (col >> 1);
            if (rlo < TOTAL_ROWS)
                g_proj8[(size_t)rlo * 128 + ci] =
                    pack_e4m3x2((c[mt][nt][0] + bx) * inv[mt * 2],
                                (c[mt][nt][1] + by) * inv[mt * 2]);
            if (rhi < TOTAL_ROWS)
                g_proj8[(size_t)rhi * 128 + ci] =
                    pack_e4m3x2((c[mt][nt][2] + bx) * inv[mt * 2 + 1],
                                (c[mt][nt][3] + by) * inv[mt * 2 + 1]);
        }
    }
}

// ---------------------------------------------------------------------------
// Loss (R14): 168 blocks x 512 threads, M64 x N128 x K256 in e4m3 (m16n8k32),
// launched with PDL: prologue (tables) runs pre-sync, data loads post-sync.
#define LSMA 0
#define LSMB 17408                 // A: 64*272
#define LTRG 52224                 // B: 128*272
#define LSM_BYTES (LTRG + 512 + 512 + 128)

__global__ void __launch_bounds__(512)
loss_mma_kernel(float* __restrict__ out)
{
    extern __shared__ char sm[];
    const uint32_t smb = smem_u32(sm);
    int* targ  = (int*)(sm + LTRG);
    int* tinfo = (int*)(sm + LTRG + 512);

    const int tid = threadIdx.x;
    const int l   = tid & 31;
    const int w   = tid >> 5;
    const int my  = w >> 3;          // 0..1
    const int cx  = w & 7;           // 0..7
    const int b   = blockIdx.x;

    int S, K, vl, chunk, mtile, qbase, pbase, aid0;
    if (b < 144) {
        int t = b / 72, rem = b % 72;
        vl = rem / 12;
        int r2 = rem % 12;
        mtile = r2 / 6; chunk = r2 % 6;
        S = 100; K = 50;
        qbase = t * 3600; pbase = t * 900;
        aid0  = t * 600 + vl * 100;
    } else {
        int bs = b - 144;
        int t2 = bs / 12;
        int rem = bs % 12;
        vl = rem / 2; chunk = rem % 2; mtile = 0;
        S = 20; K = 10;
        qbase = 7200 + t2 * 720; pbase = 1800 + t2 * 180;
        aid0  = 1200 + t2 * 120 + vl * 20;
    }
    const int NTARG = 6 * S + 3 * K;
    const int diag_base = qbase + vl * 7 * S;
    const int mrow0 = mtile * 64;

    // prologue: tables depend only on block id — runs before proj completes
    if (tid < 128) {
        int n = chunk * 128 + tid;
        int row = 0, info = 0;
        if (n < 6 * S) {
            int xy = n / S, ts = n - xy * S;
            row  = qbase + (xy * 6 + vl) * S + ts;
            info = ts | ((xy == vl) ? 0x10000 : 0) | 0x40000;
        } else if (n < NTARG) {
            int cc = n - 6 * S;
            int o = cc / K, k = cc - o * K;
            row  = Q_ROWS + pbase + (o * 6 + vl) * K + k;
            info = 0x20000 | 0x40000;
        }
        targ[tid]  = row;
        tinfo[tid] = info;
    }
    __syncthreads();

    // wait for proj grid (and its g_proj8/g_pos/g_neg writes) to complete
    cudaGridDependencySynchronize();

    for (int i = tid; i < 64 * 16; i += 512) {
        int r = i >> 4, q = i & 15;
        int gr = mrow0 + r;
        int arow = diag_base + (gr < S ? gr : 0);
        *(float4*)(sm + LSMA + r * FPITCH + q * 16) =
            ((const float4*)g_proj8)[(size_t)arow * 16 + q];
    }
    for (int i = tid; i < 128 * 16; i += 512) {
        int r = i >> 4, q = i & 15;
        *(float4*)(sm + LSMB + r * FPITCH + q * 16) =
            ((const float4*)g_proj8)[(size_t)targ[r] * 16 + q];
    }
    __syncthreads();

    const uint32_t a_base = smb + LSMA +
        (my * 32 + ((l >> 3) & 1) * 8 + (l & 7)) * FPITCH + (l >> 4) * 16;
    const uint32_t b_base = smb + LSMB +
        (cx * 16 + ((l >> 4) & 1) * 8 + (l & 7)) * FPITCH + ((l >> 3) & 1) * 16;

    float c[2][2][4];
    #pragma unroll
    for (int mt = 0; mt < 2; mt++)
        #pragma unroll
        for (int nt = 0; nt < 2; nt++)
            #pragma unroll
            for (int j = 0; j < 4; j++) c[mt][nt][j] = 0.f;

    #pragma unroll
    for (int kk = 0; kk < 8; kk++) {
        uint32_t a[8];
        ldsm_x4(a,     a_base + kk * 32);
        ldsm_x4(a + 4, a_base + kk * 32 + 16 * FPITCH);
        uint32_t b4[4];
        ldsm_x4(b4, b_base + kk * 32);
        mma16832fp8(c[0][0], a,     b4);
        mma16832fp8(c[1][0], a + 4, b4);
        mma16832fp8(c[0][1], a,     b4 + 2);
        mma16832fp8(c[1][1], a + 4, b4 + 2);
    }

    const int g  = l >> 2;
    const int q2 = (l & 3) * 2;
    float pacc[4] = {0.f, 0.f, 0.f, 0.f};
    float nacc[4] = {0.f, 0.f, 0.f, 0.f};

    int rowg[4];
    #pragma unroll
    for (int s = 0; s < 4; s++)
        rowg[s] = mrow0 + my * 32 + (s >> 1) * 16 + (s & 1) * 8 + g;

    #pragma unroll
    for (int nt = 0; nt < 2; nt++) {
        #pragma unroll
        for (int jl = 0; jl < 2; jl++) {
            int info = tinfo[cx * 16 + nt * 8 + q2 + jl];
            if (info & 0x40000) {
                int ts = info & 0xFFFF;
                #pragma unroll
                for (int mt = 0; mt < 2; mt++) {
                    #pragma unroll
                    for (int jh = 0; jh < 2; jh++) {
                        int s = mt * 2 + jh;
                        if (rowg[s] < S) {
                            float e = __expf(2.0f * c[mt][nt][jh * 2 + jl]);
                            if (info & 0x20000)        nacc[s] += e;
                            else if (info & 0x10000) { if (ts != rowg[s]) nacc[s] += e; }
                            else if (ts == rowg[s])    pacc[s] += e;
                        }
                    }
                }
            }
        }
    }

    #pragma unroll
    for (int s = 0; s < 4; s++) {
        pacc[s] += __shfl_xor_sync(0xffffffffu, pacc[s], 1);
        pacc[s] += __shfl_xor_sync(0xffffffffu, pacc[s], 2);
        nacc[s] += __shfl_xor_sync(0xffffffffu, nacc[s], 1);
        nacc[s] += __shfl_xor_sync(0xffffffffu, nacc[s], 2);
    }
    if ((l & 3) == 0) {
        #pragma unroll
        for (int s = 0; s < 4; s++) {
            if (rowg[s] < S) {
                if (pacc[s] != 0.f) atomicAdd(&g_pos[aid0 + rowg[s]], pacc[s]);
                if (nacc[s] != 0.f) atomicAdd(&g_neg[aid0 + rowg[s]], nacc[s]);
            }
        }
    }

    // ---- fused finalize ----
    __shared__ unsigned int is_last;
    __threadfence();
    __syncthreads();
    if (tid == 0)
        is_last = (atomicAdd(&g_ctr, 1u) == (unsigned)(gridDim.x - 1));
    __syncthreads();
    if (is_last) {
        float loc = 0.f;
        for (int i = tid; i < N_ANCHORS; i += 512) {
            float p = g_pos[i], n = g_neg[i];
            loc += -logf(p / (p + n));
        }
        loc += __shfl_xor_sync(0xffffffffu, loc, 16);
        loc += __shfl_xor_sync(0xffffffffu, loc, 8);
        loc += __shfl_xor_sync(0xffffffffu, loc, 4);
        loc += __shfl_xor_sync(0xffffffffu, loc, 2);
        loc += __shfl_xor_sync(0xffffffffu, loc, 1);
        float* red = (float*)(sm + LTRG + 1024);
        if (l == 0) red[w] = loc;
        __syncthreads();
        if (w == 0) {
            float s = (l < 16) ? red[l] : 0.f;
            s += __shfl_xor_sync(0xffffffffu, s, 8);
            s += __shfl_xor_sync(0xffffffffu, s, 4);
            s += __shfl_xor_sync(0xffffffffu, s, 2);
            s += __shfl_xor_sync(0xffffffffu, s, 1);
            if (l == 0) out[0] = s * (1.0f / 1440.0f);
        }
    }
}

// ---------------------------------------------------------------------------
extern "C" void kernel_launch(void* const* d_in, const int* in_sizes, int n_in,
                              void* d_out, int out_size)
{
    const float* E    = (const float*)d_in[0];
    const float* W1   = (const float*)d_in[1];
    const float* b1   = (const float*)d_in[2];
    const float* W2   = (const float*)d_in[3];
    const float* b2   = (const float*)d_in[4];
    const int*   idxp = (const int*)d_in[5];
    const int*   idxr = (const int*)d_in[6];
    const int*   negp = (const int*)d_in[7];
    const int*   negr = (const int*)d_in[8];
    float* out = (float*)d_out;
    (void)in_sizes; (void)n_in; (void)out_size;

    cudaFuncSetAttribute(proj_mma_kernel,
                         cudaFuncAttributeMaxDynamicSharedMemorySize, SM_BYTES);
    cudaFuncSetAttribute(loss_mma_kernel,
                         cudaFuncAttributeMaxDynamicSharedMemorySize, LSM_BYTES);

    proj_mma_kernel<<<PROJ_BLOCKS, 512, SM_BYTES>>>(E, W1, b1, W2, b2,
                                                    idxp, idxr, negp, negr);

    // PDL launch: loss prologue overlaps proj tail + launch latency
    cudaLaunchConfig_t cfg = {};
    cfg.gridDim = dim3(LOSS_BLOCKS, 1, 1);
    cfg.blockDim = dim3(512, 1, 1);
    cfg.dynamicSmemBytes = LSM_BYTES;
    cfg.stream = 0;
    cudaLaunchAttribute attrs[1];
    attrs[0].id = cudaLaunchAttributeProgrammaticStreamSerialization;
    attrs[0].val.programmaticStreamSerializationAllowed = 1;
    cfg.attrs = attrs;
    cfg.numAttrs = 1;
    cudaLaunchKernelEx(&cfg, loss_mma_kernel, out);
}